// round 10
// baseline (speedup 1.0000x reference)
#include <cuda_runtime.h>

// ============================================================================
// QCNN 8-qubit circuit — exact algebraic reduction to a 3x3 bilinear form.
// Single fused kernel, 128 CTAs x 512 threads (65536 threads, 1 elem/thread).
// Communication-free W build: every lane computes its W element directly from
// the shared trig table (A3·A2·A1 in registers, shallow FMA tree), one
// __syncwarp total, S gathered via pipelined shuffles.
//
// Math (verified R1-R9, rel_err ~1e-7): CNOTs couple only disjoint qubit
// pairs; <Z_0> depends only on the (0,1) 2-qubit subsystem; batch-independent
// params make the 3-layer circuit one fixed 4x4 complex unitary W; with the
// real product input state and double-angle identities:
//     z   = (1, cos x0, sin x0) · M · (1, cos x1, sin x1)^T,  M real 3x3
//     out = sigmoid(weight * z)      (weight folded into M)
// ============================================================================

struct Cx { float re, im; };

__device__ __forceinline__ Cx cmul(Cx a, Cx b) {
    return { fmaf(a.re, b.re, -a.im * b.im), fmaf(a.re, b.im, a.im * b.re) };
}
__device__ __forceinline__ Cx cfma(Cx a, Cx b, Cx acc) {
    acc.re = fmaf(a.re, b.re, fmaf(-a.im, b.im, acc.re));
    acc.im = fmaf(a.re, b.im, fmaf( a.im, b.re, acc.im));
    return acc;
}

// Build both rows of a single-qubit unitary U = Rz(g)Ry(b)Rz(a) from its 6
// trig values:  row0 = [( cb*cp, -cb*sp), (-sb*cm, -sb*sm)]
//               row1 = [( sb*cm, -sb*sm), ( cb*cp,  cb*sp)]
__device__ __forceinline__ void make_U(const float* T, Cx (&u)[2][2]) {
    float cb = T[0], sb = T[1], cp = T[2], sp = T[3], cm = T[4], sm = T[5];
    u[0][0] = {  cb * cp, -cb * sp };
    u[0][1] = { -sb * cm, -sb * sm };
    u[1][0] = {  sb * cm, -sb * sm };
    u[1][1] = {  cb * cp,  cb * sp };
}

__global__ void __launch_bounds__(512) qcnn_fused_kernel(
    const float* __restrict__ x,
    const float* __restrict__ params,
    const float* __restrict__ weight,
    float* __restrict__ out,
    int n)
{
    __shared__ float sTrig[16][36];           // per-warp: 12 trig x 3 layers

    const unsigned FULL = 0xFFFFFFFFu;
    int tid  = threadIdx.x;
    int wid  = tid >> 5;
    int lane = tid & 31;
    int i = blockIdx.x * 512 + tid;

    // ---- Issue the batch-data load first; everything overlaps it ----------
    float2 xv = make_float2(0.0f, 0.0f);
    if (i < n)
        xv = *reinterpret_cast<const float2*>(x + (size_t)i * 8);
    float wgt = __ldg(weight);

    // ---- per-element trig, hoisted into the shadow of the build -----------
    float S0, C0, S1, C1;
    __sincosf(xv.x, &S0, &C0);
    __sincosf(xv.y, &S1, &C1);

    // ---- 18 build angles, one per lane ------------------------------------
    if (lane < 18) {
        int l = lane / 6, rem = lane - l * 6;
        int q = rem / 3, combo = rem - q * 3;
        const float* p = params + l * 24 + q * 3;       // a,b,g contiguous
        float ang;
        if (combo == 0)      ang = 0.5f * p[1];              // b/2
        else if (combo == 1) ang = 0.5f * (p[0] + p[2]);     // (a+g)/2
        else                 ang = 0.5f * (p[0] - p[2]);     // (a-g)/2
        float s, c;
        __sincosf(ang, &s, &c);
        sTrig[wid][(l * 12) + q * 6 + combo * 2 + 0] = c;
        sTrig[wid][(l * 12) + q * 6 + combo * 2 + 1] = s;
    }
    __syncwarp();                             // the ONLY sync in the kernel

    // ---- communication-free W element: lane (r,c) computes W[r][c] --------
    // A_l[rr][cc] = U0_l[s(rr)>>1][cc>>1] * U1_l[s(rr)&1][cc&1],
    // s(rr) = CNOT row remap = 0,1,3,2. W = A3 * A2 * A1.
    int r = (lane >> 2) & 3, c = lane & 3;
    int cb1 = (c >> 1) & 1, cb0 = c & 1;      // column bits (runtime selects)
    int sr = (r >= 2) ? (5 - r) : r;
    int rb1 = sr >> 1, rb0 = sr & 1;          // row bits (runtime selects)

    Cx W;
    {
        const float* TL = &sTrig[wid][0];

        // Layer 1: column c of A1.  s(j) for j=0..3 is 0,1,3,2.
        Cx u0[2][2], u1[2][2];
        make_U(TL + 0, u0);  make_U(TL + 6, u1);
        Cx A1c[4];
        {
            // columns selected by runtime bits cb1 (for U0) / cb0 (for U1)
            Cx a0 = cb1 ? u0[0][1] : u0[0][0];
            Cx a1 = cb1 ? u0[1][1] : u0[1][0];
            Cx b0 = cb0 ? u1[0][1] : u1[0][0];
            Cx b1 = cb0 ? u1[1][1] : u1[1][0];
            A1c[0] = cmul(a0, b0);    // s=0 -> (0,0)
            A1c[1] = cmul(a0, b1);    // s=1 -> (0,1)
            A1c[2] = cmul(a1, b1);    // j=2 -> s=3 -> (1,1)
            A1c[3] = cmul(a1, b0);    // j=3 -> s=2 -> (1,0)
        }

        // Layer 2: B[k] = sum_j A2[k][j] * A1c[j]  (all indices compile-time)
        make_U(TL + 12, u0);  make_U(TL + 18, u1);
        Cx B[4];
        #pragma unroll
        for (int k = 0; k < 4; k++) {
            int sk = (k >= 2) ? (5 - k) : k;
            Cx acc = { 0.0f, 0.0f };
            #pragma unroll
            for (int j = 0; j < 4; j++) {
                Cx a2 = cmul(u0[sk >> 1][j >> 1], u1[sk & 1][j & 1]);
                acc = cfma(a2, A1c[j], acc);
            }
            B[k] = acc;
        }

        // Layer 3: W[r][c] = sum_k A3[r][k] * B[k]  (row r via runtime bits)
        make_U(TL + 24, u0);  make_U(TL + 30, u1);
        Cx a0 = rb1 ? u0[1][0] : u0[0][0];    // U0[rb1][0]
        Cx a1 = rb1 ? u0[1][1] : u0[0][1];    // U0[rb1][1]
        Cx b0 = rb0 ? u1[1][0] : u1[0][0];    // U1[rb0][0]
        Cx b1 = rb0 ? u1[1][1] : u1[0][1];    // U1[rb0][1]
        Cx A3r[4] = { cmul(a0, b0), cmul(a0, b1), cmul(a1, b0), cmul(a1, b1) };

        Cx acc = { 0.0f, 0.0f };
        #pragma unroll
        for (int k = 0; k < 4; k++)
            acc = cfma(A3r[k], B[k], acc);
        W = acc;
    }

    // ---- S via pipelined shuffles: lane (a,b)=(r,c) gathers W columns -----
    // S[a][b] = sum_rr d_rr (Wre[rr][a]Wre[rr][b] + Wim[rr][a]Wim[rr][b])
    float s_ab;
    {
        float ra[4], ia[4], rb[4], ib[4];
        #pragma unroll
        for (int rr = 0; rr < 4; rr++) {
            ra[rr] = __shfl_sync(FULL, W.re, rr * 4 + r);   // W[rr][a], a=r
            ia[rr] = __shfl_sync(FULL, W.im, rr * 4 + r);
            rb[rr] = __shfl_sync(FULL, W.re, rr * 4 + c);   // W[rr][b], b=c
            ib[rr] = __shfl_sync(FULL, W.im, rr * 4 + c);
        }
        float sp = fmaf(ra[0], rb[0], ia[0] * ib[0])
                 + fmaf(ra[1], rb[1], ia[1] * ib[1]);
        float sn = fmaf(ra[2], rb[2], ia[2] * ib[2])
                 + fmaf(ra[3], rb[3], ia[3] * ib[3]);
        s_ab = sp - sn;
    }

    // Broadcast the 10 needed S entries; every lane folds them into M.
    float s00 = __shfl_sync(FULL, s_ab, 0);
    float s11 = __shfl_sync(FULL, s_ab, 5);
    float s22 = __shfl_sync(FULL, s_ab, 10);
    float s33 = __shfl_sync(FULL, s_ab, 15);
    float s01 = __shfl_sync(FULL, s_ab, 1);
    float s23 = __shfl_sync(FULL, s_ab, 11);
    float s02 = __shfl_sync(FULL, s_ab, 2);
    float s13 = __shfl_sync(FULL, s_ab, 7);
    float s03 = __shfl_sync(FULL, s_ab, 3);
    float s12 = __shfl_sync(FULL, s_ab, 6);

    float q4 = 0.25f * wgt, q2 = 0.5f * wgt;
    float m00 = q4 * (s00 + s11 + s22 + s33);
    float m01 = q4 * (s00 - s11 + s22 - s33);
    float m02 = q2 * (s01 + s23);
    float m10 = q4 * (s00 + s11 - s22 - s33);
    float m11 = q4 * (s00 - s11 - s22 + s33);
    float m12 = q2 * (s01 - s23);
    float m20 = q2 * (s02 + s13);
    float m21 = q2 * (s02 - s13);
    float m22 = q2 * (s03 + s12);

    if (i >= n) return;

    // z = (1,C0,S0) M (1,C1,S1)^T   (weight already folded into M)
    float t0 = fmaf(m02, S1, fmaf(m01, C1, m00));
    float t1 = fmaf(m12, S1, fmaf(m11, C1, m10));
    float t2 = fmaf(m22, S1, fmaf(m21, C1, m20));
    float z  = fmaf(S0, t2, fmaf(C0, t1, t0));

    out[i] = __fdividef(1.0f, 1.0f + __expf(-z));
}

extern "C" void kernel_launch(void* const* d_in, const int* in_sizes, int n_in,
                              void* d_out, int out_size) {
    const float* x      = (const float*)d_in[0];   // (65536, 8) fp32
    const float* params = (const float*)d_in[1];   // (3, 8, 3) fp32
    const float* weight = (const float*)d_in[2];   // scalar fp32
    float* out = (float*)d_out;                    // (65536,) fp32

    int n = in_sizes[0] / 8;                       // 65536

    int threads = 512;
    int blocks = (n + threads - 1) / threads;      // 128 blocks
    qcnn_fused_kernel<<<blocks, threads>>>(x, params, weight, out, n);
}